// round 15
// baseline (speedup 1.0000x reference)
#include <cuda_runtime.h>
#include <cstdint>

#define BB 1024      // batch
#define DD 512       // feature dim
#define MM 256       // modes
#define THRESHV 1.0f
#define RB 4         // batch rows per scores-block (was 8)
#define SCTH 512     // scores block threads
#define NCHUNK 4     // mode chunks for the fused kernel
#define MCH (MM / NCHUNK)   // 64 modes per chunk
#define LB 8         // load batch (MLP group) in fused kernel
#define WTS 257      // padded Wt row stride (floats): 256 modes + 1

// partial mixed accumulators, one slab per mode-chunk (deterministic reduce)
__device__ float g_partial[NCHUNK][BB * DD];   // 8 MB static scratch

// ---------------------------------------------------------------------------
// Kernel 1: scores[b,m] = softmax_m( dot(x[b,:], W[m,:]) + bias[m] )
// 256 blocks x 512 threads (RB=4): ~1.7 blocks/SM, up to 4 resident ->
// occupancy ceiling 100% (vs 50% at 1024thr/1blk) and no idle SMs.
// thread t: mode m = t&255, row-group g = t>>8 (owns rows 2g, 2g+1).
// W staged via smem in 16-float k-tiles, transposed Wt[k][m] (stride 257,
// compute-side conflict-free), both staging float4s prefetched.
// k-order per (row,mode) identical to R14 -> bit-identical logits.
// smem: xs 8KB + Wt 16.1KB + logits 4KB = ~28KB static.
// ---------------------------------------------------------------------------
__global__ __launch_bounds__(SCTH)
void poly_scores_kernel(const float* __restrict__ x,
                        const float* __restrict__ W,
                        const float* __restrict__ bias,
                        float* __restrict__ scores)
{
    __shared__ float4 xs[RB * (DD / 4)];       // 8 KB (512 float4)
    __shared__ float  Wt[16 * WTS];            // 16 k-slots x 257 floats
    __shared__ float  logits[RB][MM];          // 4 KB

    const int b0 = blockIdx.x * RB;
    const int t  = threadIdx.x;                // 0..511
    const int m  = t & 255;                    // mode
    const int g  = t >> 8;                     // row group -> rows 2g, 2g+1

    // load 4 x-rows: one float4 per thread, coalesced
    xs[t] = reinterpret_cast<const float4*>(x + (size_t)b0 * DD)[t];

    // staging mapping: two float4 of W per thread per tile (i = t, t+512)
    const int sm0 = t >> 2;                    // staging mode row (0..127)
    const int sj0 = t & 3;
    const int sm1 = sm0 + 128;                 // second half (128..255)
    const float4* Wg = reinterpret_cast<const float4*>(W);
    const size_t wb0 = (size_t)sm0 * (DD / 4) + sj0;
    const size_t wb1 = (size_t)sm1 * (DD / 4) + sj0;

    float a0 = 0.0f, a1 = 0.0f;
    float4 v0 = Wg[wb0];                       // prefetch tile 0 (both halves)
    float4 v1 = Wg[wb1];

    const float4* xr0 = &xs[(2 * g)     * (DD / 4)];
    const float4* xr1 = &xs[(2 * g + 1) * (DD / 4)];

    #pragma unroll 1
    for (int k0 = 0; k0 < DD / 4; k0 += 4) {   // 32 tiles of 16 k-floats
        __syncthreads();                        // Wt free; (1st iter: xs ready)
        Wt[(sj0 * 4 + 0) * WTS + sm0] = v0.x;   // transposed stores, <=2-way
        Wt[(sj0 * 4 + 1) * WTS + sm0] = v0.y;
        Wt[(sj0 * 4 + 2) * WTS + sm0] = v0.z;
        Wt[(sj0 * 4 + 3) * WTS + sm0] = v0.w;
        Wt[(sj0 * 4 + 0) * WTS + sm1] = v1.x;
        Wt[(sj0 * 4 + 1) * WTS + sm1] = v1.y;
        Wt[(sj0 * 4 + 2) * WTS + sm1] = v1.z;
        Wt[(sj0 * 4 + 3) * WTS + sm1] = v1.w;
        if (k0 + 4 < DD / 4) {                  // prefetch next tile
            v0 = Wg[wb0 + k0 + 4];
            v1 = Wg[wb1 + k0 + 4];
        }
        __syncthreads();

        #pragma unroll
        for (int kk = 0; kk < 4; ++kk) {
            const float w0 = Wt[(kk * 4 + 0) * WTS + m];   // conflict-free
            const float w1 = Wt[(kk * 4 + 1) * WTS + m];
            const float w2 = Wt[(kk * 4 + 2) * WTS + m];
            const float w3 = Wt[(kk * 4 + 3) * WTS + m];
            const float4 xv0 = xr0[k0 + kk];               // warp broadcast
            const float4 xv1 = xr1[k0 + kk];
            a0 = fmaf(w0, xv0.x, a0); a0 = fmaf(w1, xv0.y, a0);
            a0 = fmaf(w2, xv0.z, a0); a0 = fmaf(w3, xv0.w, a0);
            a1 = fmaf(w0, xv1.x, a1); a1 = fmaf(w1, xv1.y, a1);
            a1 = fmaf(w2, xv1.z, a1); a1 = fmaf(w3, xv1.w, a1);
        }
    }

    const float bv = bias[m];
    logits[2 * g][m]     = a0 + bv;            // each group owns its rows
    logits[2 * g + 1][m] = a1 + bv;
    __syncthreads();

    // softmax: warps 0..3 handle rows 0..3 (256 elems, 8 per lane)
    if (t < 32 * RB) {
        const int w    = t >> 5;
        const int lane = t & 31;
        float vv[8];
        float mx = -1e30f;
        #pragma unroll
        for (int j = 0; j < 8; ++j) { vv[j] = logits[w][lane + 32 * j]; mx = fmaxf(mx, vv[j]); }
        #pragma unroll
        for (int o = 16; o > 0; o >>= 1) mx = fmaxf(mx, __shfl_xor_sync(0xFFFFFFFFu, mx, o));
        float s = 0.0f;
        #pragma unroll
        for (int j = 0; j < 8; ++j) { vv[j] = __expf(vv[j] - mx); s += vv[j]; }
        #pragma unroll
        for (int o = 16; o > 0; o >>= 1) s += __shfl_xor_sync(0xFFFFFFFFu, s, o);
        const float inv = 1.0f / s;

        float* srow = scores + (size_t)(b0 + w) * MM;
        #pragma unroll
        for (int j = 0; j < 8; ++j) srow[lane + 32 * j] = vv[j] * inv;
    }
}

// ---------------------------------------------------------------------------
// Kernel 2 (UNCHANGED — measured ~163us, ~6.5TB/s): grid (1024 b, 4 chunks)
// x 128 threads, explicit 8-wide load batching for MLP_p1=8.
// ---------------------------------------------------------------------------
__global__ __launch_bounds__(128, 8)
void poly_fused_chunk_kernel(const float* __restrict__ x,
                             const float* __restrict__ mem,
                             const float* __restrict__ scores,
                             float* __restrict__ mem_new)
{
    __shared__ float s_sc[MCH];

    const int b  = blockIdx.x;
    const int c  = blockIdx.y;
    const int m0 = c * MCH;
    const int t  = threadIdx.x;                // 0..127 (float4 lane over D)

    if (t < MCH) s_sc[t] = scores[(size_t)b * MM + m0 + t];
    __syncthreads();

    const size_t base = (size_t)b * (DD / 4) + t;   // in float4 units
    const float4 xv   = reinterpret_cast<const float4*>(x)[base];

    const float4* m4 = reinterpret_cast<const float4*>(mem);
    float4*       o4 = reinterpret_cast<float4*>(mem_new);

    float4 acc = make_float4(0.f, 0.f, 0.f, 0.f);
    const size_t stride = (size_t)(BB * DD / 4);    // float4 per mode

    #pragma unroll
    for (int mo = 0; mo < MCH; mo += LB) {
        float4 mv[LB];
        #pragma unroll
        for (int j = 0; j < LB; ++j)
            mv[j] = __ldcs(m4 + base + (size_t)(m0 + mo + j) * stride);

        #pragma unroll
        for (int j = 0; j < LB; ++j) {
            const int   m    = m0 + mo + j;
            const float beta = (float)m / 257.0f;

            float4 mn;
            mn.x = fmaf(beta, mv[j].x, xv.x) - (mv[j].x > THRESHV ? 1.0f : 0.0f);
            mn.y = fmaf(beta, mv[j].y, xv.y) - (mv[j].y > THRESHV ? 1.0f : 0.0f);
            mn.z = fmaf(beta, mv[j].z, xv.z) - (mv[j].z > THRESHV ? 1.0f : 0.0f);
            mn.w = fmaf(beta, mv[j].w, xv.w) - (mv[j].w > THRESHV ? 1.0f : 0.0f);

            __stcs(o4 + base + (size_t)m * stride, mn);

            const float sc = s_sc[mo + j];
            acc.x += (mn.x - THRESHV > 0.0f) ? sc : 0.0f;
            acc.y += (mn.y - THRESHV > 0.0f) ? sc : 0.0f;
            acc.z += (mn.z - THRESHV > 0.0f) ? sc : 0.0f;
            acc.w += (mn.w - THRESHV > 0.0f) ? sc : 0.0f;
        }
    }

    reinterpret_cast<float4*>(&g_partial[c][0])[base] = acc;
}

// ---------------------------------------------------------------------------
// Kernel 3: mixed = sum over the 4 chunk partials. 18 MB traffic, ~3us.
// ---------------------------------------------------------------------------
__global__ __launch_bounds__(256)
void poly_reduce_kernel(float* __restrict__ mixed)
{
    const size_t i = (size_t)blockIdx.x * 256 + threadIdx.x;  // float4 index
    const float4 p0 = reinterpret_cast<const float4*>(&g_partial[0][0])[i];
    const float4 p1 = reinterpret_cast<const float4*>(&g_partial[1][0])[i];
    const float4 p2 = reinterpret_cast<const float4*>(&g_partial[2][0])[i];
    const float4 p3 = reinterpret_cast<const float4*>(&g_partial[3][0])[i];
    float4 r;
    r.x = (p0.x + p1.x) + (p2.x + p3.x);
    r.y = (p0.y + p1.y) + (p2.y + p3.y);
    r.z = (p0.z + p1.z) + (p2.z + p3.z);
    r.w = (p0.w + p1.w) + (p2.w + p3.w);
    reinterpret_cast<float4*>(mixed)[i] = r;
}

// ---------------------------------------------------------------------------
// Launch: outputs packed as [mixed (B*D) | mem_new (M*B*D) | scores (B*M)]
// ---------------------------------------------------------------------------
extern "C" void kernel_launch(void* const* d_in, const int* in_sizes, int n_in,
                              void* d_out, int out_size)
{
    const float* x    = (const float*)d_in[0];   // [B, D]
    const float* mem  = (const float*)d_in[1];   // [M, B, D]
    const float* W    = (const float*)d_in[2];   // [M, D]
    const float* bias = (const float*)d_in[3];   // [M]

    float* out     = (float*)d_out;
    float* mixed   = out;                                          // B*D
    float* mem_new = out + (size_t)BB * DD;                        // M*B*D
    float* scores  = out + (size_t)BB * DD + (size_t)MM * BB * DD; // B*M

    poly_scores_kernel<<<BB / RB, SCTH>>>(x, W, bias, scores);
    poly_fused_chunk_kernel<<<dim3(BB, NCHUNK), 128>>>(x, mem, scores, mem_new);
    poly_reduce_kernel<<<(BB * DD / 4) / 256, 256>>>(mixed);
}

// round 16
// speedup vs baseline: 1.0293x; 1.0293x over previous
#include <cuda_runtime.h>
#include <cstdint>

#define BB 1024      // batch
#define DD 512       // feature dim
#define MM 256       // modes
#define THRESHV 1.0f
#define RB 8         // batch rows per scores-block
#define KSPLIT 4     // k-quarters for scores gemm
#define KQ4 32       // float4 per k-quarter (128 floats)
#define NCHUNK 4     // mode chunks for the fused kernel
#define MCH (MM / NCHUNK)   // 64 modes per chunk
#define LB 8         // load batch (MLP group) in fused kernel
#define WTS 257      // padded Wt row stride (floats): 256 modes + 1

// partial mixed accumulators, one slab per mode-chunk (deterministic reduce)
__device__ float g_partial[NCHUNK][BB * DD];   // 8 MB static scratch
// logit partials per k-quarter: [kq][b][m], 4 MB
__device__ float g_logitsP[KSPLIT][BB * MM];

// ---------------------------------------------------------------------------
// Kernel 1a: logit partials. grid (128 row-groups, 4 k-quarters) x 1024 thr.
// thread t: mode m = t&255, row-group g = t>>8 (rows 2g, 2g+1).
// Each block covers k in [kq*128, kq*128+128): 8 tiles of 16 k-floats,
// transposed conflict-free Wt staging (as R14), prefetched. 512 blocks ->
// 2 resident 1024-thread blocks/SM (launch_bounds(1024,2)) ~100% occ,
// and only 16 barriers per block (vs 64).
// smem: Wt 16.1KB + xs 4KB = ~20KB -> 2 blocks/SM fits easily.
// ---------------------------------------------------------------------------
__global__ __launch_bounds__(1024, 2)
void poly_scores_gemm(const float* __restrict__ x,
                      const float* __restrict__ W)
{
    __shared__ float  Wt[16 * WTS];            // 16 k-slots x 257 floats
    __shared__ float4 xs[RB * KQ4];            // 8 rows x 32 float4 (k-quarter)

    const int b0 = blockIdx.x * RB;
    const int kq = blockIdx.y;                 // k-quarter
    const int t  = threadIdx.x;                // 0..1023
    const int m  = t & 255;                    // mode
    const int g  = t >> 8;                     // row group -> rows 2g, 2g+1

    // load 8 x-rows' k-quarter: 256 float4, coalesced (32 consecutive per row)
    if (t < RB * KQ4) {
        const int r = t >> 5;                  // row 0..7
        const int j = t & 31;                  // float4 within quarter
        xs[t] = reinterpret_cast<const float4*>(x)[(size_t)(b0 + r) * (DD / 4) + kq * KQ4 + j];
    }

    // staging mapping: one float4 of W per thread per tile
    const int sm = t >> 2;                     // staging mode row (0..255)
    const int sj = t & 3;                      // float4 index within tile
    const float4* Wg = reinterpret_cast<const float4*>(W);
    const size_t wbase = (size_t)sm * (DD / 4) + kq * KQ4 + sj;

    float a0 = 0.0f, a1 = 0.0f;
    float4 v = Wg[wbase];                      // prefetch tile 0

    const float4* xr0 = &xs[(2 * g)     * KQ4];
    const float4* xr1 = &xs[(2 * g + 1) * KQ4];

    #pragma unroll 1
    for (int tile = 0; tile < 8; ++tile) {     // 8 tiles of 16 k-floats
        __syncthreads();                        // Wt free; (1st iter: xs ready)
        Wt[(sj * 4 + 0) * WTS + sm] = v.x;      // transposed stores, <=2-way
        Wt[(sj * 4 + 1) * WTS + sm] = v.y;
        Wt[(sj * 4 + 2) * WTS + sm] = v.z;
        Wt[(sj * 4 + 3) * WTS + sm] = v.w;
        if (tile < 7) v = Wg[wbase + (tile + 1) * 4];   // prefetch next
        __syncthreads();

        #pragma unroll
        for (int kk = 0; kk < 4; ++kk) {
            const float w0 = Wt[(kk * 4 + 0) * WTS + m];   // conflict-free
            const float w1 = Wt[(kk * 4 + 1) * WTS + m];
            const float w2 = Wt[(kk * 4 + 2) * WTS + m];
            const float w3 = Wt[(kk * 4 + 3) * WTS + m];
            const float4 xv0 = xr0[tile * 4 + kk];         // warp broadcast
            const float4 xv1 = xr1[tile * 4 + kk];
            a0 = fmaf(w0, xv0.x, a0); a0 = fmaf(w1, xv0.y, a0);
            a0 = fmaf(w2, xv0.z, a0); a0 = fmaf(w3, xv0.w, a0);
            a1 = fmaf(w0, xv1.x, a1); a1 = fmaf(w1, xv1.y, a1);
            a1 = fmaf(w2, xv1.z, a1); a1 = fmaf(w3, xv1.w, a1);
        }
    }

    // coalesced partial writes (m consecutive across t)
    g_logitsP[kq][(size_t)(b0 + 2 * g)     * MM + m] = a0;
    g_logitsP[kq][(size_t)(b0 + 2 * g + 1) * MM + m] = a1;
}

// ---------------------------------------------------------------------------
// Kernel 1b: sum k-quarter partials (+bias), softmax per row -> scores.
// 128 blocks x 256 threads; partials are L2-hot (4MB). ~3us.
// ---------------------------------------------------------------------------
__global__ __launch_bounds__(256)
void poly_scores_softmax(const float* __restrict__ bias,
                         float* __restrict__ scores)
{
    __shared__ float logits[RB][MM];

    const int b0 = blockIdx.x * RB;
    const int t  = threadIdx.x;                // 0..255 == mode

    const float bv = bias[t];
    #pragma unroll
    for (int r = 0; r < RB; ++r) {
        const size_t i = (size_t)(b0 + r) * MM + t;   // coalesced
        logits[r][t] = ((g_logitsP[0][i] + g_logitsP[1][i])
                      + g_logitsP[2][i]) + g_logitsP[3][i] + bv;
    }
    __syncthreads();

    // softmax: warp w handles row w (256 elems, 8 per lane)
    const int w    = t >> 5;
    const int lane = t & 31;
    float vv[8];
    float mx = -1e30f;
    #pragma unroll
    for (int j = 0; j < 8; ++j) { vv[j] = logits[w][lane + 32 * j]; mx = fmaxf(mx, vv[j]); }
    #pragma unroll
    for (int o = 16; o > 0; o >>= 1) mx = fmaxf(mx, __shfl_xor_sync(0xFFFFFFFFu, mx, o));
    float s = 0.0f;
    #pragma unroll
    for (int j = 0; j < 8; ++j) { vv[j] = __expf(vv[j] - mx); s += vv[j]; }
    #pragma unroll
    for (int o = 16; o > 0; o >>= 1) s += __shfl_xor_sync(0xFFFFFFFFu, s, o);
    const float inv = 1.0f / s;

    float* srow = scores + (size_t)(b0 + w) * MM;
    #pragma unroll
    for (int j = 0; j < 8; ++j) srow[lane + 32 * j] = vv[j] * inv;
}

// ---------------------------------------------------------------------------
// Kernel 2 (UNCHANGED — measured ~163us, ~6.6TB/s): grid (1024 b, 4 chunks)
// x 128 threads, explicit 8-wide load batching for MLP_p1=8.
// ---------------------------------------------------------------------------
__global__ __launch_bounds__(128, 8)
void poly_fused_chunk_kernel(const float* __restrict__ x,
                             const float* __restrict__ mem,
                             const float* __restrict__ scores,
                             float* __restrict__ mem_new)
{
    __shared__ float s_sc[MCH];

    const int b  = blockIdx.x;
    const int c  = blockIdx.y;
    const int m0 = c * MCH;
    const int t  = threadIdx.x;                // 0..127 (float4 lane over D)

    if (t < MCH) s_sc[t] = scores[(size_t)b * MM + m0 + t];
    __syncthreads();

    const size_t base = (size_t)b * (DD / 4) + t;   // in float4 units
    const float4 xv   = reinterpret_cast<const float4*>(x)[base];

    const float4* m4 = reinterpret_cast<const float4*>(mem);
    float4*       o4 = reinterpret_cast<float4*>(mem_new);

    float4 acc = make_float4(0.f, 0.f, 0.f, 0.f);
    const size_t stride = (size_t)(BB * DD / 4);    // float4 per mode

    #pragma unroll
    for (int mo = 0; mo < MCH; mo += LB) {
        float4 mv[LB];
        #pragma unroll
        for (int j = 0; j < LB; ++j)
            mv[j] = __ldcs(m4 + base + (size_t)(m0 + mo + j) * stride);

        #pragma unroll
        for (int j = 0; j < LB; ++j) {
            const int   m    = m0 + mo + j;
            const float beta = (float)m / 257.0f;

            float4 mn;
            mn.x = fmaf(beta, mv[j].x, xv.x) - (mv[j].x > THRESHV ? 1.0f : 0.0f);
            mn.y = fmaf(beta, mv[j].y, xv.y) - (mv[j].y > THRESHV ? 1.0f : 0.0f);
            mn.z = fmaf(beta, mv[j].z, xv.z) - (mv[j].z > THRESHV ? 1.0f : 0.0f);
            mn.w = fmaf(beta, mv[j].w, xv.w) - (mv[j].w > THRESHV ? 1.0f : 0.0f);

            __stcs(o4 + base + (size_t)m * stride, mn);

            const float sc = s_sc[mo + j];
            acc.x += (mn.x - THRESHV > 0.0f) ? sc : 0.0f;
            acc.y += (mn.y - THRESHV > 0.0f) ? sc : 0.0f;
            acc.z += (mn.z - THRESHV > 0.0f) ? sc : 0.0f;
            acc.w += (mn.w - THRESHV > 0.0f) ? sc : 0.0f;
        }
    }

    reinterpret_cast<float4*>(&g_partial[c][0])[base] = acc;
}

// ---------------------------------------------------------------------------
// Kernel 3: mixed = sum over the 4 chunk partials. 18 MB traffic, ~3us.
// ---------------------------------------------------------------------------
__global__ __launch_bounds__(256)
void poly_reduce_kernel(float* __restrict__ mixed)
{
    const size_t i = (size_t)blockIdx.x * 256 + threadIdx.x;  // float4 index
    const float4 p0 = reinterpret_cast<const float4*>(&g_partial[0][0])[i];
    const float4 p1 = reinterpret_cast<const float4*>(&g_partial[1][0])[i];
    const float4 p2 = reinterpret_cast<const float4*>(&g_partial[2][0])[i];
    const float4 p3 = reinterpret_cast<const float4*>(&g_partial[3][0])[i];
    float4 r;
    r.x = (p0.x + p1.x) + (p2.x + p3.x);
    r.y = (p0.y + p1.y) + (p2.y + p3.y);
    r.z = (p0.z + p1.z) + (p2.z + p3.z);
    r.w = (p0.w + p1.w) + (p2.w + p3.w);
    reinterpret_cast<float4*>(mixed)[i] = r;
}

// ---------------------------------------------------------------------------
// Launch: outputs packed as [mixed (B*D) | mem_new (M*B*D) | scores (B*M)]
// ---------------------------------------------------------------------------
extern "C" void kernel_launch(void* const* d_in, const int* in_sizes, int n_in,
                              void* d_out, int out_size)
{
    const float* x    = (const float*)d_in[0];   // [B, D]
    const float* mem  = (const float*)d_in[1];   // [M, B, D]
    const float* W    = (const float*)d_in[2];   // [M, D]
    const float* bias = (const float*)d_in[3];   // [M]

    float* out     = (float*)d_out;
    float* mixed   = out;                                          // B*D
    float* mem_new = out + (size_t)BB * DD;                        // M*B*D
    float* scores  = out + (size_t)BB * DD + (size_t)MM * BB * DD; // B*M

    poly_scores_gemm<<<dim3(BB / RB, KSPLIT), 1024>>>(x, W);
    poly_scores_softmax<<<BB / RB, 256>>>(bias, scores);
    poly_fused_chunk_kernel<<<dim3(BB, NCHUNK), 128>>>(x, mem, scores, mem_new);
    poly_reduce_kernel<<<(BB * DD / 4) / 256, 256>>>(mixed);
}